// round 1
// baseline (speedup 1.0000x reference)
#include <cuda_runtime.h>

#define B 64
#define CIN 512
#define HIDE 128
#define OP 512
#define HW 4096   // 64*64

// scratch for pooled y [B, CIN]
__device__ float g_y[B * CIN];

// ---------------------------------------------------------------------------
// Kernel 1: global average pool. One block per (b, c) row of 4096 floats.
// 256 threads, each loads 4 float4 (16 floats), tree reduce.
// ---------------------------------------------------------------------------
__global__ __launch_bounds__(256) void pool_kernel(const float* __restrict__ x,
                                                   float* __restrict__ y) {
    const int row = blockIdx.x;  // b*CIN + c
    const float4* p = reinterpret_cast<const float4*>(x + (size_t)row * HW);
    const int t = threadIdx.x;

    float s = 0.0f;
#pragma unroll
    for (int i = 0; i < 4; i++) {
        float4 v = p[t + i * 256];
        s += (v.x + v.y) + (v.z + v.w);
    }
    // warp reduce
#pragma unroll
    for (int o = 16; o > 0; o >>= 1) s += __shfl_xor_sync(0xFFFFFFFFu, s, o);

    __shared__ float sm[8];
    if ((t & 31) == 0) sm[t >> 5] = s;
    __syncthreads();
    if (t < 8) {
        float v = sm[t];
#pragma unroll
        for (int o = 4; o > 0; o >>= 1) v += __shfl_xor_sync(0x000000FFu, v, o);
        if (t == 0) y[row] = v * (1.0f / (float)HW);
    }
}

// ---------------------------------------------------------------------------
// Kernel 2: fused AGCA head. One block per batch, 128 threads (= HIDE).
//   y1 = y @ W1^T            [HIDE]
//   A1 = softmax(w2 * y1)
//   y2 = y1*A1 + y1 @ A2     [HIDE]
//   y3 = relu(w3 * y2)
//   out = sigmoid(y3 @ W4^T) [OP]
// ---------------------------------------------------------------------------
__global__ __launch_bounds__(128) void head_kernel(const float* __restrict__ y,
                                                   const float* __restrict__ W1,
                                                   const float* __restrict__ A2,
                                                   const float* __restrict__ w2p,
                                                   const float* __restrict__ w3p,
                                                   const float* __restrict__ W4,
                                                   float* __restrict__ out) {
    const int b = blockIdx.x;
    const int h = threadIdx.x;  // 0..127

    __shared__ float ys[CIN];
    __shared__ float y1s[HIDE];
    __shared__ float y3s[HIDE];
    __shared__ float red[4];

    // load pooled row into smem
    for (int c = h; c < CIN; c += HIDE) ys[c] = y[b * CIN + c];
    __syncthreads();

    // y1[h] = dot(ys, W1[h, :])
    float acc = 0.0f;
    const float* w1r = W1 + (size_t)h * CIN;
#pragma unroll 8
    for (int c = 0; c < CIN; c++) acc += ys[c] * w1r[c];
    y1s[h] = acc;

    // softmax(w2 * y1) over the 128 channels
    const float w2 = *w2p;
    const float z = w2 * acc;

    float m = z;
#pragma unroll
    for (int o = 16; o > 0; o >>= 1) m = fmaxf(m, __shfl_xor_sync(0xFFFFFFFFu, m, o));
    if ((h & 31) == 0) red[h >> 5] = m;
    __syncthreads();  // also publishes y1s[]
    m = fmaxf(fmaxf(red[0], red[1]), fmaxf(red[2], red[3]));

    const float e = expf(z - m);
    float ssum = e;
#pragma unroll
    for (int o = 16; o > 0; o >>= 1) ssum += __shfl_xor_sync(0xFFFFFFFFu, ssum, o);
    __syncthreads();
    if ((h & 31) == 0) red[h >> 5] = ssum;
    __syncthreads();
    ssum = (red[0] + red[1]) + (red[2] + red[3]);
    const float a1 = e / ssum;

    // y2[h] = y1[h]*A1[h] + sum_j y1[j] * A2[j, h]
    float t = acc * a1;
#pragma unroll 8
    for (int j = 0; j < HIDE; j++) t += y1s[j] * A2[j * HIDE + h];

    const float w3 = *w3p;
    y3s[h] = fmaxf(w3 * t, 0.0f);
    __syncthreads();

    // out[b, o] = sigmoid(dot(y3, W4[o, :]))
    for (int o = h; o < OP; o += HIDE) {
        const float* w4r = W4 + (size_t)o * HIDE;
        float a = 0.0f;
#pragma unroll 8
        for (int j = 0; j < HIDE; j++) a += y3s[j] * w4r[j];
        out[b * OP + o] = 1.0f / (1.0f + expf(-a));
    }
}

extern "C" void kernel_launch(void* const* d_in, const int* in_sizes, int n_in,
                              void* d_out, int out_size) {
    const float* x  = (const float*)d_in[0];
    const float* W1 = (const float*)d_in[1];
    const float* A2 = (const float*)d_in[2];
    const float* w2 = (const float*)d_in[3];
    const float* w3 = (const float*)d_in[4];
    const float* W4 = (const float*)d_in[5];
    float* out = (float*)d_out;

    float* yscratch;
    cudaGetSymbolAddress((void**)&yscratch, g_y);

    pool_kernel<<<B * CIN, 256>>>(x, yscratch);
    head_kernel<<<B, 128>>>(yscratch, W1, A2, w2, w3, W4, out);
}

// round 2
// speedup vs baseline: 1.7318x; 1.7318x over previous
#include <cuda_runtime.h>

#define B 64
#define CIN 512
#define HIDE 128
#define OP 512
#define HW 4096   // 64*64

// scratch for pooled y [B, CIN]
__device__ float g_y[B * CIN];

// ---------------------------------------------------------------------------
// Kernel 1: global average pool. One block per (b, c) row of 4096 floats.
// 256 threads, each loads 4 float4 (16 floats) streaming, tree reduce.
// ---------------------------------------------------------------------------
__global__ __launch_bounds__(256) void pool_kernel(const float* __restrict__ x,
                                                   float* __restrict__ y) {
    const int row = blockIdx.x;  // b*CIN + c
    const float4* p = reinterpret_cast<const float4*>(x + (size_t)row * HW);
    const int t = threadIdx.x;

    float s = 0.0f;
#pragma unroll
    for (int i = 0; i < 4; i++) {
        float4 v = __ldcs(&p[t + i * 256]);
        s += (v.x + v.y) + (v.z + v.w);
    }
#pragma unroll
    for (int o = 16; o > 0; o >>= 1) s += __shfl_xor_sync(0xFFFFFFFFu, s, o);

    __shared__ float sm[8];
    if ((t & 31) == 0) sm[t >> 5] = s;
    __syncthreads();
    if (t < 8) {
        float v = sm[t];
#pragma unroll
        for (int o = 4; o > 0; o >>= 1) v += __shfl_xor_sync(0x000000FFu, v, o);
        if (t == 0) y[row] = v * (1.0f / (float)HW);
    }
}

// ---------------------------------------------------------------------------
// Kernel 2: fused AGCA head. One block per batch, 1024 threads (32 warps).
// All GEMV loads are warp-coalesced (lanes span the contraction dim),
// reductions via shuffles — no serial load->FMA dependence chains.
// ---------------------------------------------------------------------------
__global__ __launch_bounds__(1024) void head_kernel(const float* __restrict__ y,
                                                    const float* __restrict__ W1,
                                                    const float* __restrict__ A2,
                                                    const float* __restrict__ w2p,
                                                    const float* __restrict__ w3p,
                                                    const float* __restrict__ W4,
                                                    float* __restrict__ out) {
    const int b    = blockIdx.x;
    const int tid  = threadIdx.x;
    const int wid  = tid >> 5;   // 0..31
    const int lane = tid & 31;

    __shared__ float ys[CIN];
    __shared__ float y1s[HIDE];
    __shared__ float a1s[HIDE];
    __shared__ float y3s[HIDE];
    __shared__ float red[8];

    // ---- load pooled row (coalesced) ----
    if (tid < CIN) ys[tid] = y[b * CIN + tid];
    __syncthreads();

    // ---- GEMV1: y1[h] = dot(ys, W1[h,:]), warp wid handles h = wid*4 + {0..3}
    #pragma unroll
    for (int i = 0; i < 4; i++) {
        const int h = (wid << 2) + i;
        const float* w1r = W1 + (size_t)h * CIN;
        float acc = 0.0f;
        #pragma unroll
        for (int k = 0; k < CIN / 32; k++) {
            const int c = lane + (k << 5);
            acc += ys[c] * __ldg(&w1r[c]);
        }
        #pragma unroll
        for (int o = 16; o > 0; o >>= 1) acc += __shfl_xor_sync(0xFFFFFFFFu, acc, o);
        if (lane == 0) y1s[h] = acc;
    }
    __syncthreads();

    // ---- softmax(w2 * y1) over 128 channels: first 4 warps ----
    const float w2 = __ldg(w2p);
    if (tid < HIDE) {
        const float z = w2 * y1s[tid];
        float m = z;
        #pragma unroll
        for (int o = 16; o > 0; o >>= 1) m = fmaxf(m, __shfl_xor_sync(0xFFFFFFFFu, m, o));
        if (lane == 0) red[wid] = m;
    }
    __syncthreads();
    if (tid < HIDE) {
        const float m = fmaxf(fmaxf(red[0], red[1]), fmaxf(red[2], red[3]));
        const float e = expf(w2 * y1s[tid] - m);
        a1s[tid] = e;   // unnormalized for now
        float ssum = e;
        #pragma unroll
        for (int o = 16; o > 0; o >>= 1) ssum += __shfl_xor_sync(0xFFFFFFFFu, ssum, o);
        if (lane == 0) red[4 + wid] = ssum;
    }
    __syncthreads();

    // ---- y2/y3: threads 0..127, h = tid; A2 loads coalesced over h ----
    if (tid < HIDE) {
        const float ssum = (red[4] + red[5]) + (red[6] + red[7]);
        const float a1 = a1s[tid] / ssum;
        float t = y1s[tid] * a1;
        #pragma unroll 8
        for (int j = 0; j < HIDE; j++) t += y1s[j] * __ldg(&A2[j * HIDE + tid]);
        const float w3 = __ldg(w3p);
        y3s[tid] = fmaxf(w3 * t, 0.0f);
    }
    __syncthreads();

    // ---- GEMV4: out[b,o] = sigmoid(dot(y3, W4[o,:])), warp handles 16 o's ----
    #pragma unroll
    for (int i = 0; i < 16; i++) {
        const int o = (wid << 4) + i;
        const float* w4r = W4 + (size_t)o * HIDE;
        float acc = 0.0f;
        #pragma unroll
        for (int k = 0; k < HIDE / 32; k++) {
            const int j = lane + (k << 5);
            acc += y3s[j] * __ldg(&w4r[j]);
        }
        #pragma unroll
        for (int off = 16; off > 0; off >>= 1) acc += __shfl_xor_sync(0xFFFFFFFFu, acc, off);
        if (lane == 0) out[b * OP + o] = 1.0f / (1.0f + expf(-acc));
    }
}

extern "C" void kernel_launch(void* const* d_in, const int* in_sizes, int n_in,
                              void* d_out, int out_size) {
    const float* x  = (const float*)d_in[0];
    const float* W1 = (const float*)d_in[1];
    const float* A2 = (const float*)d_in[2];
    const float* w2 = (const float*)d_in[3];
    const float* w3 = (const float*)d_in[4];
    const float* W4 = (const float*)d_in[5];
    float* out = (float*)d_out;

    float* yscratch;
    cudaGetSymbolAddress((void**)&yscratch, g_y);

    pool_kernel<<<B * CIN, 256>>>(x, yscratch);
    head_kernel<<<B, 1024>>>(yscratch, W1, A2, w2, w3, W4, out);
}

// round 3
// speedup vs baseline: 1.7806x; 1.0282x over previous
#include <cuda_runtime.h>

#define B 64
#define CIN 512
#define HIDE 128
#define OP 512
#define HW 4096   // 64*64

// scratch
__device__ float g_y[B * CIN];     // pooled
__device__ float g_y3[B * HIDE];   // post-relu hidden

// ---------------------------------------------------------------------------
// Kernel 1: global average pool (HBM-bound, at spec — unchanged).
// ---------------------------------------------------------------------------
__global__ __launch_bounds__(256) void pool_kernel(const float* __restrict__ x,
                                                   float* __restrict__ y) {
    const int row = blockIdx.x;
    const float4* p = reinterpret_cast<const float4*>(x + (size_t)row * HW);
    const int t = threadIdx.x;

    float s = 0.0f;
#pragma unroll
    for (int i = 0; i < 4; i++) {
        float4 v = __ldcs(&p[t + i * 256]);
        s += (v.x + v.y) + (v.z + v.w);
    }
#pragma unroll
    for (int o = 16; o > 0; o >>= 1) s += __shfl_xor_sync(0xFFFFFFFFu, s, o);

    __shared__ float sm[8];
    if ((t & 31) == 0) sm[t >> 5] = s;
    __syncthreads();
    if (t < 8) {
        float v = sm[t];
#pragma unroll
        for (int o = 4; o > 0; o >>= 1) v += __shfl_xor_sync(0x000000FFu, v, o);
        if (t == 0) y[row] = v * (1.0f / (float)HW);
    }
}

// ---------------------------------------------------------------------------
// Kernel 2a: y3 = relu(w3 * (y1*softmax(w2*y1) + y1@A2)), y1 = y@W1^T.
// One block per batch, 1024 threads. All loads batched for MLP before
// any reduction; shfl chains interleaved.
// ---------------------------------------------------------------------------
__global__ __launch_bounds__(1024) void head_a_kernel(const float* __restrict__ y,
                                                      const float* __restrict__ W1,
                                                      const float* __restrict__ A2,
                                                      const float* __restrict__ w2p,
                                                      const float* __restrict__ w3p,
                                                      float* __restrict__ y3out) {
    const int b    = blockIdx.x;
    const int tid  = threadIdx.x;
    const int wid  = tid >> 5;
    const int lane = tid & 31;

    __shared__ float ys[CIN];
    __shared__ float y1s[HIDE];
    __shared__ float a1s[HIDE];
    __shared__ float red[8];

    if (tid < CIN) ys[tid] = y[b * CIN + tid];
    __syncthreads();

    // GEMV1: warp wid -> h = wid*4 + {0..3}; 64 independent loads up front.
    {
        const int h0 = wid << 2;
        const float* r0 = W1 + (size_t)(h0 + 0) * CIN;
        const float* r1 = W1 + (size_t)(h0 + 1) * CIN;
        const float* r2 = W1 + (size_t)(h0 + 2) * CIN;
        const float* r3 = W1 + (size_t)(h0 + 3) * CIN;
        float a0 = 0.f, a1 = 0.f, a2 = 0.f, a3 = 0.f;
#pragma unroll
        for (int k = 0; k < CIN / 32; k++) {
            const int c = lane + (k << 5);
            const float yv = ys[c];
            a0 += yv * __ldg(r0 + c);
            a1 += yv * __ldg(r1 + c);
            a2 += yv * __ldg(r2 + c);
            a3 += yv * __ldg(r3 + c);
        }
#pragma unroll
        for (int o = 16; o > 0; o >>= 1) {
            a0 += __shfl_xor_sync(0xFFFFFFFFu, a0, o);
            a1 += __shfl_xor_sync(0xFFFFFFFFu, a1, o);
            a2 += __shfl_xor_sync(0xFFFFFFFFu, a2, o);
            a3 += __shfl_xor_sync(0xFFFFFFFFu, a3, o);
        }
        if (lane == 0) {
            y1s[h0 + 0] = a0; y1s[h0 + 1] = a1;
            y1s[h0 + 2] = a2; y1s[h0 + 3] = a3;
        }
    }
    __syncthreads();

    // softmax(w2 * y1) over 128 channels (first 4 warps)
    const float w2 = __ldg(w2p);
    if (tid < HIDE) {
        const float z = w2 * y1s[tid];
        float m = z;
#pragma unroll
        for (int o = 16; o > 0; o >>= 1) m = fmaxf(m, __shfl_xor_sync(0xFFFFFFFFu, m, o));
        if (lane == 0) red[wid] = m;
    }
    __syncthreads();
    if (tid < HIDE) {
        const float m = fmaxf(fmaxf(red[0], red[1]), fmaxf(red[2], red[3]));
        const float e = expf(w2 * y1s[tid] - m);
        a1s[tid] = e;
        float ssum = e;
#pragma unroll
        for (int o = 16; o > 0; o >>= 1) ssum += __shfl_xor_sync(0xFFFFFFFFu, ssum, o);
        if (lane == 0) red[4 + wid] = ssum;
    }
    __syncthreads();

    // y2/y3: h = tid (<128); A2 coalesced across h, unrolled for MLP.
    if (tid < HIDE) {
        const float ssum = (red[4] + red[5]) + (red[6] + red[7]);
        const float a1n = a1s[tid] / ssum;
        float t = y1s[tid] * a1n;
#pragma unroll 16
        for (int j = 0; j < HIDE; j++) t += y1s[j] * __ldg(&A2[j * HIDE + tid]);
        const float w3 = __ldg(w3p);
        y3out[b * HIDE + tid] = fmaxf(w3 * t, 0.0f);
    }
}

// ---------------------------------------------------------------------------
// Kernel 2b: out[b,o] = sigmoid(dot(y3[b,:], W4[o,:])).
// Grid 256 = 64 batches x 4 segments of 128 outputs. 256 threads (8 warps),
// warp owns 16 outputs; all 64 loads issued before the 16 interleaved
// shfl-reduction chains.
// ---------------------------------------------------------------------------
__global__ __launch_bounds__(256) void head_b_kernel(const float* __restrict__ y3,
                                                     const float* __restrict__ W4,
                                                     float* __restrict__ out) {
    const int b    = blockIdx.x >> 2;
    const int seg  = blockIdx.x & 3;
    const int tid  = threadIdx.x;
    const int wid  = tid >> 5;
    const int lane = tid & 31;

    __shared__ float y3s[HIDE];
    if (tid < HIDE) y3s[tid] = y3[b * HIDE + tid];
    __syncthreads();

    const int o_base = (seg << 7) + (wid << 4);  // seg*128 + wid*16
    float acc[16];
#pragma unroll
    for (int i = 0; i < 16; i++) acc[i] = 0.0f;

#pragma unroll
    for (int k = 0; k < HIDE / 32; k++) {
        const int j = lane + (k << 5);
        const float yv = y3s[j];
#pragma unroll
        for (int i = 0; i < 16; i++)
            acc[i] += yv * __ldg(&W4[(size_t)(o_base + i) * HIDE + j]);
    }

#pragma unroll
    for (int off = 16; off > 0; off >>= 1) {
#pragma unroll
        for (int i = 0; i < 16; i++)
            acc[i] += __shfl_xor_sync(0xFFFFFFFFu, acc[i], off);
    }

    if (lane == 0) {
#pragma unroll
        for (int i = 0; i < 16; i++)
            out[b * OP + o_base + i] = 1.0f / (1.0f + expf(-acc[i]));
    }
}

extern "C" void kernel_launch(void* const* d_in, const int* in_sizes, int n_in,
                              void* d_out, int out_size) {
    const float* x  = (const float*)d_in[0];
    const float* W1 = (const float*)d_in[1];
    const float* A2 = (const float*)d_in[2];
    const float* w2 = (const float*)d_in[3];
    const float* w3 = (const float*)d_in[4];
    const float* W4 = (const float*)d_in[5];
    float* out = (float*)d_out;

    float *yscratch, *y3scratch;
    cudaGetSymbolAddress((void**)&yscratch, g_y);
    cudaGetSymbolAddress((void**)&y3scratch, g_y3);

    pool_kernel<<<B * CIN, 256>>>(x, yscratch);
    head_a_kernel<<<B, 1024>>>(yscratch, W1, A2, w2, w3, y3scratch);
    head_b_kernel<<<B * 4, 256>>>(y3scratch, W4, out);
}

// round 4
// speedup vs baseline: 1.7982x; 1.0099x over previous
#include <cuda_runtime.h>

#define B 64
#define CIN 512
#define HIDE 128
#define OP 512
#define HW 4096   // 64*64

// scratch for pooled y [B, CIN]
__device__ float g_y[B * CIN];

__device__ __forceinline__ void prefetch_l2(const void* p) {
    asm volatile("prefetch.global.L2 [%0];" :: "l"(p));
}

// ---------------------------------------------------------------------------
// Kernel 1: global average pool. One block per (b, c) row of 4096 floats.
// Triggers PDL completion early so the head kernel can begin prefetching
// weights while the pool's final waves drain.
// ---------------------------------------------------------------------------
__global__ __launch_bounds__(256) void pool_kernel(const float* __restrict__ x,
                                                   float* __restrict__ y) {
    cudaTriggerProgrammaticLaunchCompletion();

    const int row = blockIdx.x;
    const float4* p = reinterpret_cast<const float4*>(x + (size_t)row * HW);
    const int t = threadIdx.x;

    float s = 0.0f;
#pragma unroll
    for (int i = 0; i < 4; i++) {
        float4 v = __ldcs(&p[t + i * 256]);
        s += (v.x + v.y) + (v.z + v.w);
    }
#pragma unroll
    for (int o = 16; o > 0; o >>= 1) s += __shfl_xor_sync(0xFFFFFFFFu, s, o);

    __shared__ float sm[8];
    if ((t & 31) == 0) sm[t >> 5] = s;
    __syncthreads();
    if (t < 8) {
        float v = sm[t];
#pragma unroll
        for (int o = 4; o > 0; o >>= 1) v += __shfl_xor_sync(0x000000FFu, v, o);
        if (t == 0) y[row] = v * (1.0f / (float)HW);
    }
}

// ---------------------------------------------------------------------------
// Kernel 2: fully fused AGCA head. One block per batch, 1024 threads.
// Launched with PDL: prefetches its weight slice into L2 BEFORE the grid
// dependency resolves, then syncs and computes.
// ---------------------------------------------------------------------------
__global__ __launch_bounds__(1024) void head_kernel(const float* __restrict__ y,
                                                    const float* __restrict__ W1,
                                                    const float* __restrict__ A2,
                                                    const float* __restrict__ w2p,
                                                    const float* __restrict__ w3p,
                                                    const float* __restrict__ W4,
                                                    float* __restrict__ out) {
    const int b    = blockIdx.x;
    const int tid  = threadIdx.x;
    const int wid  = tid >> 5;
    const int lane = tid & 31;

    // ---- L2 prefetch of this block's 1/64 slice of the weights ----
    // W1: 256KB = 2048 lines -> 32/block (threads 0-31)
    // W4: 256KB = 2048 lines -> 32/block (threads 32-63)
    // A2:  64KB =  512 lines ->  8/block (threads 64-71)
    {
        const char* w1c = (const char*)W1;
        const char* w4c = (const char*)W4;
        const char* a2c = (const char*)A2;
        if (tid < 32) {
            prefetch_l2(w1c + ((size_t)b * 32 + tid) * 128);
        } else if (tid < 64) {
            prefetch_l2(w4c + ((size_t)b * 32 + (tid - 32)) * 128);
        } else if (tid < 72) {
            prefetch_l2(a2c + ((size_t)b * 8 + (tid - 64)) * 128);
        }
    }

    cudaGridDependencySynchronize();

    __shared__ float ys[CIN];
    __shared__ float y1s[HIDE];
    __shared__ float a1s[HIDE];
    __shared__ float y3s[HIDE];
    __shared__ float red[8];

    if (tid < CIN) ys[tid] = y[b * CIN + tid];
    __syncthreads();

    // ---- GEMV1: warp wid -> h = wid*4 + {0..3}; batched loads ----
    {
        const int h0 = wid << 2;
        const float* r0 = W1 + (size_t)(h0 + 0) * CIN;
        const float* r1 = W1 + (size_t)(h0 + 1) * CIN;
        const float* r2 = W1 + (size_t)(h0 + 2) * CIN;
        const float* r3 = W1 + (size_t)(h0 + 3) * CIN;
        float a0 = 0.f, a1 = 0.f, a2 = 0.f, a3 = 0.f;
#pragma unroll
        for (int k = 0; k < CIN / 32; k++) {
            const int c = lane + (k << 5);
            const float yv = ys[c];
            a0 += yv * __ldg(r0 + c);
            a1 += yv * __ldg(r1 + c);
            a2 += yv * __ldg(r2 + c);
            a3 += yv * __ldg(r3 + c);
        }
#pragma unroll
        for (int o = 16; o > 0; o >>= 1) {
            a0 += __shfl_xor_sync(0xFFFFFFFFu, a0, o);
            a1 += __shfl_xor_sync(0xFFFFFFFFu, a1, o);
            a2 += __shfl_xor_sync(0xFFFFFFFFu, a2, o);
            a3 += __shfl_xor_sync(0xFFFFFFFFu, a3, o);
        }
        if (lane == 0) {
            y1s[h0 + 0] = a0; y1s[h0 + 1] = a1;
            y1s[h0 + 2] = a2; y1s[h0 + 3] = a3;
        }
    }
    __syncthreads();

    // ---- softmax(w2 * y1) over 128 channels (first 4 warps) ----
    const float w2 = __ldg(w2p);
    if (tid < HIDE) {
        const float z = w2 * y1s[tid];
        float m = z;
#pragma unroll
        for (int o = 16; o > 0; o >>= 1) m = fmaxf(m, __shfl_xor_sync(0xFFFFFFFFu, m, o));
        if (lane == 0) red[wid] = m;
    }
    __syncthreads();
    if (tid < HIDE) {
        const float m = fmaxf(fmaxf(red[0], red[1]), fmaxf(red[2], red[3]));
        const float e = expf(w2 * y1s[tid] - m);
        a1s[tid] = e;
        float ssum = e;
#pragma unroll
        for (int o = 16; o > 0; o >>= 1) ssum += __shfl_xor_sync(0xFFFFFFFFu, ssum, o);
        if (lane == 0) red[4 + wid] = ssum;
    }
    __syncthreads();

    // ---- y2/y3: h = tid (<128); A2 coalesced over h ----
    if (tid < HIDE) {
        const float ssum = (red[4] + red[5]) + (red[6] + red[7]);
        const float a1n = a1s[tid] / ssum;
        float t = y1s[tid] * a1n;
#pragma unroll 16
        for (int j = 0; j < HIDE; j++) t += y1s[j] * __ldg(&A2[j * HIDE + tid]);
        const float w3 = __ldg(w3p);
        y3s[tid] = fmaxf(w3 * t, 0.0f);
    }
    __syncthreads();

    // ---- GEMV4: warp wid owns outputs wid*16..wid*16+15 (2 passes of 8) ----
#pragma unroll
    for (int pass = 0; pass < 2; pass++) {
        const int o_base = (wid << 4) + (pass << 3);
        float acc[8];
#pragma unroll
        for (int i = 0; i < 8; i++) acc[i] = 0.0f;
#pragma unroll
        for (int k = 0; k < HIDE / 32; k++) {
            const int j = lane + (k << 5);
            const float yv = y3s[j];
#pragma unroll
            for (int i = 0; i < 8; i++)
                acc[i] += yv * __ldg(&W4[(size_t)(o_base + i) * HIDE + j]);
        }
#pragma unroll
        for (int off = 16; off > 0; off >>= 1) {
#pragma unroll
            for (int i = 0; i < 8; i++)
                acc[i] += __shfl_xor_sync(0xFFFFFFFFu, acc[i], off);
        }
        if (lane == 0) {
#pragma unroll
            for (int i = 0; i < 8; i++)
                out[b * OP + o_base + i] = 1.0f / (1.0f + expf(-acc[i]));
        }
    }
}

extern "C" void kernel_launch(void* const* d_in, const int* in_sizes, int n_in,
                              void* d_out, int out_size) {
    const float* x  = (const float*)d_in[0];
    const float* W1 = (const float*)d_in[1];
    const float* A2 = (const float*)d_in[2];
    const float* w2 = (const float*)d_in[3];
    const float* w3 = (const float*)d_in[4];
    const float* W4 = (const float*)d_in[5];
    float* out = (float*)d_out;

    float* yscratch;
    cudaGetSymbolAddress((void**)&yscratch, g_y);

    pool_kernel<<<B * CIN, 256>>>(x, yscratch);

    // Head kernel with programmatic dependent launch: starts (and prefetches
    // weights into L2) while the pool's final wave drains.
    cudaLaunchConfig_t cfg = {};
    cfg.gridDim = dim3(B);
    cfg.blockDim = dim3(1024);
    cfg.dynamicSmemBytes = 0;
    cfg.stream = 0;
    cudaLaunchAttribute attr[1];
    attr[0].id = cudaLaunchAttributeProgrammaticStreamSerialization;
    attr[0].val.programmaticStreamSerializationAllowed = 1;
    cfg.attrs = attr;
    cfg.numAttrs = 1;
    cudaLaunchKernelEx(&cfg, head_kernel, (const float*)yscratch, W1, A2, w2, w3, W4, out);
}